// round 16
// baseline (speedup 1.0000x reference)
#include <cuda_runtime.h>
#include <math_constants.h>

#define HH 1024
#define WW 1024
#define CC 128
#define NITER 8
#define TWO_RHO 71.6f         // 2 * sqrt(16^2 + 32^2) for a 32x64 region
#define FULLM 0xFFFFFFFFu
#define NBLK 512              // one CTA per 32-row x 64-col region

// 4 rotating cluster position buffers (row,col interleaved).
// Invariant: g_pos[1] is all-zero at kernel entry (static init covers the
// first run; block 0 re-zeroes it at k==6 each run for the next replay).
__device__ float g_pos[4][2 * CC];
// software grid barrier: counter and generation on SEPARATE 128B lines
__device__ __align__(128) unsigned g_cnt[32];
__device__ __align__(128) unsigned g_gen[32];

__device__ __forceinline__ unsigned ld_acquire_gpu(const unsigned* p) {
    unsigned v;
    asm volatile("ld.acquire.gpu.u32 %0, [%1];" : "=r"(v) : "l"(p) : "memory");
    return v;
}

// All cross-CTA data traffic is L2-native (global atomics + __ldcg), so
// scoped release/acquire atomics give full ordering with no membar/CCTL.
__device__ __forceinline__ void grid_barrier(unsigned target) {
    __syncthreads();
    if (threadIdx.x == 0) {
        unsigned old;
        asm volatile("atom.add.acq_rel.gpu.u32 %0, [%1], %2;"
                     : "=r"(old) : "l"(&g_cnt[0]), "r"(1u) : "memory");
        if (old == NBLK - 1u) {
            asm volatile("st.relaxed.gpu.u32 [%0], %1;"
                         :: "l"(&g_cnt[0]), "r"(0u) : "memory");
            asm volatile("red.add.release.gpu.u32 [%0], %1;"
                         :: "l"(&g_gen[0]), "r"(1u) : "memory");
        } else {
            unsigned g = ld_acquire_gpu(&g_gen[0]);
            int spins = 0;
            while ((int)(g - target) < 0) {
                if (++spins > 4) __nanosleep(40);   // hot-spin first, then doze
                g = ld_acquire_gpu(&g_gen[0]);
            }
        }
    }
    __syncthreads();
}

// warp-wide min of a uint (nonneg float bits are order-isomorphic)
__device__ __forceinline__ unsigned warp_min_u32(unsigned v) {
    unsigned r;
    asm volatile("redux.sync.min.u32 %0, %1, 0xffffffff;" : "=r"(r) : "r"(v));
    return r;
}

__global__ void __launch_bounds__(256, 4) km_all_kernel(
    const float* __restrict__ clusters,
    const float* __restrict__ heatmap,
    float* __restrict__ out)
{
    __shared__ float s_acc[2 * CC];

    const int t = threadIdx.x;
    const int lane = t & 31;
    // 32-row x 64-col region per CTA; 8 consecutive pixels per thread
    const int region_c = (blockIdx.x & 15) * 64;
    const int region_r = (blockIdx.x >> 4) * 32;
    const int row  = region_r + (t >> 3);
    const int col0 = region_c + (t & 7) * 8;
    const float frow = (float)row;
    const float fc0  = (float)col0;
    const float cy = (float)region_r + 15.5f;
    const float cx = (float)region_c + 31.5f;

    // heatmap values for this thread's 8 pixels: constant across iterations
    float h[8];
    {
        const float4 a = *reinterpret_cast<const float4*>(heatmap + row * WW + col0);
        const float4 b = *reinterpret_cast<const float4*>(heatmap + row * WW + col0 + 4);
        h[0] = a.x; h[1] = a.y; h[2] = a.z; h[3] = a.w;
        h[4] = b.x; h[5] = b.y; h[6] = b.z; h[7] = b.w;
    }

    s_acc[t] = 0.0f;
    __syncthreads();

    // base generation (monotone across replays); every CTA reads it before any
    // bump can occur (a bump needs all NBLK arrivals, each preceded by a read)
    unsigned tgt = ld_acquire_gpu(&g_gen[0]);

    #pragma unroll 1
    for (int k = 0; k < NITER; ++k) {
        const float* cin = (k == 0) ? clusters : &g_pos[k & 3][0];
        float* cout = (k == NITER - 1) ? out : &g_pos[(k + 1) & 3][0];

        // ---- Phase A (per-warp, register-resident; NO block syncs) ----
        // every warp loads ALL 128 clusters (4 per lane), so one redux
        // gives the full min; candidates stay in registers, fetched in
        // Phase B via shfl from the owner lane.
        const float2* cin2 = reinterpret_cast<const float2*>(cin);
        float2 c4[4];
        float  d2[4];
        float m = CUDART_INF_F;
        #pragma unroll
        for (int q = 0; q < 4; ++q) {
            // L2 load: positions were produced by global atomics on other SMs
            c4[q] = __ldcg(cin2 + q * 32 + lane);
            const float dr = cy - c4[q].x, dc = cx - c4[q].y;
            d2[q] = fmaf(dr, dr, dc * dc);
            m = fminf(m, d2[q]);
        }
        const float md2 = __uint_as_float(warp_min_u32(__float_as_uint(m)));

        // first exactly-(0,0) cluster (empty clusters collapse there);
        // later (0,0) dups can never win strict-< argmin -> drop them.
        // Other bitwise dups are rare and harmless (strict < keeps first).
        unsigned zb[4];
        #pragma unroll
        for (int q = 0; q < 4; ++q)
            zb[q] = __ballot_sync(FULLM, (c4[q].x == 0.0f) && (c4[q].y == 0.0f));
        int firstZero = 1 << 30;
        #pragma unroll
        for (int q = 3; q >= 0; --q)
            if (zb[q]) firstZero = q * 32 + (__ffs(zb[q]) - 1);

        // cluster can win argmin for some pixel in region only if
        // d(center,c) <= minD + 2*rho; margin keeps fp error conservative
        const float minD = sqrtf(md2);
        const float thr  = minD + TWO_RHO + 4.0f + 1e-5f * minD;
        const float thr2 = thr * thr;

        unsigned kb[4];
        #pragma unroll
        for (int q = 0; q < 4; ++q) {
            const int ci = q * 32 + lane;
            const bool zz = (zb[q] >> lane) & 1u;
            kb[q] = __ballot_sync(FULLM, (d2[q] <= thr2) && !(zz && ci != firstZero));
        }

        // ---- Phase B: 8-pixel argmin over register candidates ----
        // ascending (q, lane) order == ascending original index (strict <)
        float b[8];
        int   bi[8];
        #pragma unroll
        for (int q = 0; q < 8; ++q) { b[q] = CUDART_INF_F; bi[q] = 0; }

        #pragma unroll
        for (int q = 0; q < 4; ++q) {
            unsigned mask = kb[q];             // uniform across warp
            while (mask) {
                const int src = __ffs(mask) - 1;
                mask &= mask - 1u;
                const float clx = __shfl_sync(FULLM, c4[q].x, src);
                const float cly = __shfl_sync(FULLM, c4[q].y, src);
                const int   ci  = q * 32 + src;
                const float dr  = frow - clx;
                const float dr2 = dr * dr;
                #pragma unroll
                for (int p = 0; p < 8; ++p) {
                    // ordering of max(1,sqrt(d2)) == ordering of max(1,d2)
                    const float dc = (fc0 + (float)p) - cly;
                    const float d = fmaxf(fmaf(dc, dc, dr2), 1.0f);
                    if (d < b[p]) { b[p] = d; bi[p] = ci; }
                }
            }
        }

        float w8[8];
        #pragma unroll
        for (int p = 0; p < 8; ++p)
            // weight = heatmap / max(1,sqrt(d2)) = h * rsqrt(clamped d2)
            w8[p] = h[p] * rsqrtf(b[p]);

        // ---- scatter: uniform-warp fast path, run-length fallback ----
        bool uni = true;
        #pragma unroll
        for (int p = 1; p < 8; ++p) uni = uni && (bi[p] == bi[0]);
        const int  u      = __shfl_sync(FULLM, bi[0], 0);
        const bool alluni = __all_sync(FULLM, uni && (bi[0] == u));

        if (alluni) {
            float wsum = ((w8[0] + w8[1]) + (w8[2] + w8[3]))
                       + ((w8[4] + w8[5]) + (w8[6] + w8[7]));
            float csum = 0.0f;
            #pragma unroll
            for (int p = 0; p < 8; ++p) csum = fmaf(fc0 + (float)p, w8[p], csum);
            float rsum = frow * wsum;
            #pragma unroll
            for (int o = 16; o; o >>= 1) {
                rsum += __shfl_xor_sync(FULLM, rsum, o);
                csum += __shfl_xor_sync(FULLM, csum, o);
            }
            if (lane == 0) {
                atomicAdd(&s_acc[2 * u],     rsum);
                atomicAdd(&s_acc[2 * u + 1], csum);
            }
        } else {
            int cur = bi[0];
            float wsum = w8[0], cwsum = fc0 * w8[0];
            #pragma unroll
            for (int p = 1; p < 8; ++p) {
                const float fcp = fc0 + (float)p;
                if (bi[p] == cur) { wsum += w8[p]; cwsum = fmaf(fcp, w8[p], cwsum); }
                else {
                    atomicAdd(&s_acc[2 * cur],     frow * wsum);
                    atomicAdd(&s_acc[2 * cur + 1], cwsum);
                    cur = bi[p]; wsum = w8[p]; cwsum = fcp * w8[p];
                }
            }
            atomicAdd(&s_acc[2 * cur],     frow * wsum);
            atomicAdd(&s_acc[2 * cur + 1], cwsum);
        }

        __syncthreads();
        // global accumulate; skip zeros (all contributions are >= +0);
        // re-zero own slot for the next iteration (ordered by the barrier)
        const float v = s_acc[t];
        if (v != 0.0f) atomicAdd(&cout[t], v);
        s_acc[t] = 0.0f;

        // block 0 zeroes a buffer that is idle this iteration:
        //  k<=4 : output buffer of iteration k+2
        //  k==5 : d_out (output of iteration 7)
        //  k==6 : g_pos[1] (restores entry invariant for the next replay)
        if (blockIdx.x == 0) {
            if (k <= 4)      g_pos[(k + 2) & 3][t] = 0.0f;
            else if (k == 5) out[t] = 0.0f;
            else if (k == 6) g_pos[1][t] = 0.0f;
        }

        if (k < NITER - 1) grid_barrier(++tgt);
    }
}

extern "C" void kernel_launch(void* const* d_in, const int* in_sizes, int n_in,
                              void* d_out, int out_size) {
    const float* clusters = (const float*)d_in[0];
    const float* heatmap  = (const float*)d_in[1];
    if (n_in >= 2 && in_sizes[0] != 2 * CC) {
        const float* tmp = clusters; clusters = heatmap; heatmap = tmp;
    }
    km_all_kernel<<<NBLK, 256>>>(clusters, heatmap, (float*)d_out);
}